// round 5
// baseline (speedup 1.0000x reference)
#include <cuda_runtime.h>
#include <math_constants.h>

#define B 16
#define T 32
#define WW 128
#define D 1024
#define NDBLK 32            // d-chunks for projection partials
#define DCHUNK (D / NDBLK)  // 32

// Scratch (no device allocation allowed). .bss is zero-initialized: masked-turn
// rows of g_cw are never written and stay exactly 0 across graph replays.
__device__ float g_part[2 * NDBLK * B * D];  // 4 MB
__device__ float g_q[2 * B * D];
__device__ float g_cw[B * T * D];
__device__ float g_ts[B * T];

// ---------------------------------------------------------------------------
// Kernel 1: partial projections q = source @ W (W stored [indim, outdim]).
// grid = (NDBLK, 1, 2 mats) = 64 CTAs, 256 threads. One CTA covers ALL 16
// batch rows -> W is read exactly once (8 MB total).
// ---------------------------------------------------------------------------
__global__ __launch_bounds__(256) void proj_part_kernel(
    const float* __restrict__ src, const float* __restrict__ Wword,
    const float* __restrict__ Wturn) {
  int dblk = blockIdx.x;
  int mat = blockIdx.z;
  const float* __restrict__ Wm = mat ? Wturn : Wword;
  int c4 = threadIdx.x * 4;
  int d0 = dblk * DCHUNK;

  __shared__ float s_src[DCHUNK][B];
#pragma unroll
  for (int e = threadIdx.x; e < DCHUNK * B; e += 256) {
    int dl = e >> 4, bb = e & 15;
    s_src[dl][bb] = src[bb * D + d0 + dl];
  }
  __syncthreads();

  float4 acc[B];
#pragma unroll
  for (int bb = 0; bb < B; bb++) acc[bb] = make_float4(0.f, 0.f, 0.f, 0.f);

#pragma unroll
  for (int dl = 0; dl < DCHUNK; dl++) {
    float4 wv = *reinterpret_cast<const float4*>(&Wm[(d0 + dl) * D + c4]);
#pragma unroll
    for (int bb = 0; bb < B; bb++) {
      float s = s_src[dl][bb];
      acc[bb].x = fmaf(s, wv.x, acc[bb].x);
      acc[bb].y = fmaf(s, wv.y, acc[bb].y);
      acc[bb].z = fmaf(s, wv.z, acc[bb].z);
      acc[bb].w = fmaf(s, wv.w, acc[bb].w);
    }
  }

#pragma unroll
  for (int bb = 0; bb < B; bb++) {
    float* outp = g_part + ((long)(mat * NDBLK + dblk) * B + bb) * D + c4;
    *reinterpret_cast<float4*>(outp) = acc[bb];
  }
}

// ---------------------------------------------------------------------------
// Kernel 2: reduce NDBLK partials -> g_q[2][B][D]. grid = 32 x 256 (4 MB).
// ---------------------------------------------------------------------------
__global__ __launch_bounds__(256) void reduce_q_kernel() {
  int idx = blockIdx.x * 256 + threadIdx.x;  // [2][16][256 float4]
  int mat = idx >> 12;
  int b = (idx >> 8) & 15;
  int c4 = (idx & 255) * 4;
  float4 s0 = make_float4(0.f, 0.f, 0.f, 0.f), s1 = s0, s2 = s0, s3 = s0;
#pragma unroll
  for (int j = 0; j < NDBLK; j += 4) {
    const float* bp = g_part + ((long)(mat * NDBLK + j) * B + b) * D + c4;
    float4 p0 = *reinterpret_cast<const float4*>(bp);
    float4 p1 = *reinterpret_cast<const float4*>(bp + (long)B * D);
    float4 p2 = *reinterpret_cast<const float4*>(bp + 2L * B * D);
    float4 p3 = *reinterpret_cast<const float4*>(bp + 3L * B * D);
    s0.x += p0.x; s0.y += p0.y; s0.z += p0.z; s0.w += p0.w;
    s1.x += p1.x; s1.y += p1.y; s1.z += p1.z; s1.w += p1.w;
    s2.x += p2.x; s2.y += p2.y; s2.z += p2.z; s2.w += p2.w;
    s3.x += p3.x; s3.y += p3.y; s3.z += p3.z; s3.w += p3.w;
  }
  float4 sum = make_float4(s0.x + s1.x + s2.x + s3.x, s0.y + s1.y + s2.y + s3.y,
                           s0.z + s1.z + s2.z + s3.z, s0.w + s1.w + s2.w + s3.w);
  *reinterpret_cast<float4*>(g_q + (mat * B + b) * D + c4) = sum;
}

// ---------------------------------------------------------------------------
// Kernel 3: per-(b,t) word attention, TWO-PASS (no online-softmax chain).
// 256 threads, 8 warps.
// Pass 1: warp wp scores rows wp, wp+8, ... (full-D per warp, 2 rows/iter,
//         rows independent -> loads pipeline freely). Scores -> smem.
// Softmax: warp 0, one shot over <=128 scores.
// Pass 2: warp wp owns cols [wp*128, wp*128+128); lane owns one float4.
//         Streams ALL rows (L2-resident after pass 1) with known weights.
//         acc = 4 regs; no cross-warp merge needed.
// ---------------------------------------------------------------------------
__global__ __launch_bounds__(256) void attn_kernel(
    const float* __restrict__ bank, const int* __restrict__ lens,
    const int* __restrict__ turns) {
  int t = blockIdx.x, b = blockIdx.y;
  if (t >= turns[b]) return;  // masked turn: contributes exactly 0 downstream
  int len = lens[b * T + t];
  int tid = threadIdx.x, wp = tid >> 5, lane = tid & 31;

  __shared__ float s_sc[WW];
  __shared__ float s_wt[WW];
  __shared__ float s_misc[12];

  const float* __restrict__ base = bank + (long)(b * T + t) * WW * D;

  // ---- pass 1: scores ----
  {
    float4 qw[8];
#pragma unroll
    for (int j = 0; j < 8; j++)
      qw[j] = *reinterpret_cast<const float4*>(g_q + b * D + j * 128 + lane * 4);

    int w = wp;
    for (; w + 8 < len; w += 16) {
      float4 r0[8], r1[8];
#pragma unroll
      for (int j = 0; j < 8; j++)
        r0[j] = *reinterpret_cast<const float4*>(base + w * D + j * 128 + lane * 4);
#pragma unroll
      for (int j = 0; j < 8; j++)
        r1[j] = *reinterpret_cast<const float4*>(base + (w + 8) * D + j * 128 + lane * 4);
      float p0 = 0.f, p1 = 0.f;
#pragma unroll
      for (int j = 0; j < 8; j++) {
        p0 = fmaf(qw[j].x, r0[j].x, fmaf(qw[j].y, r0[j].y,
             fmaf(qw[j].z, r0[j].z, fmaf(qw[j].w, r0[j].w, p0))));
        p1 = fmaf(qw[j].x, r1[j].x, fmaf(qw[j].y, r1[j].y,
             fmaf(qw[j].z, r1[j].z, fmaf(qw[j].w, r1[j].w, p1))));
      }
#pragma unroll
      for (int off = 16; off; off >>= 1) {
        p0 += __shfl_xor_sync(0xffffffffu, p0, off);
        p1 += __shfl_xor_sync(0xffffffffu, p1, off);
      }
      if (lane == 0) { s_sc[w] = p0; s_sc[w + 8] = p1; }
    }
    if (w < len) {
      float4 r0[8];
#pragma unroll
      for (int j = 0; j < 8; j++)
        r0[j] = *reinterpret_cast<const float4*>(base + w * D + j * 128 + lane * 4);
      float p0 = 0.f;
#pragma unroll
      for (int j = 0; j < 8; j++)
        p0 = fmaf(qw[j].x, r0[j].x, fmaf(qw[j].y, r0[j].y,
             fmaf(qw[j].z, r0[j].z, fmaf(qw[j].w, r0[j].w, p0))));
#pragma unroll
      for (int off = 16; off; off >>= 1) p0 += __shfl_xor_sync(0xffffffffu, p0, off);
      if (lane == 0) s_sc[w] = p0;
    }
  }
  __syncthreads();

  // ---- softmax over <=128 scores (warp 0) ----
  if (tid < 32) {
    float v[4];
    float mx = -CUDART_INF_F;
#pragma unroll
    for (int k = 0; k < 4; k++) {
      int i = lane + 32 * k;
      v[k] = (i < len) ? s_sc[i] : -CUDART_INF_F;
      mx = fmaxf(mx, v[k]);
    }
#pragma unroll
    for (int off = 16; off; off >>= 1)
      mx = fmaxf(mx, __shfl_xor_sync(0xffffffffu, mx, off));
    float e[4], sm = 0.f;
#pragma unroll
    for (int k = 0; k < 4; k++) {
      int i = lane + 32 * k;
      e[k] = (i < len) ? __expf(v[k] - mx) : 0.f;
      sm += e[k];
    }
#pragma unroll
    for (int off = 16; off; off >>= 1)
      sm += __shfl_xor_sync(0xffffffffu, sm, off);
#pragma unroll
    for (int k = 0; k < 4; k++) s_wt[lane + 32 * k] = e[k];
    if (lane == 0) s_misc[0] = 1.f / sm;
  }
  __syncthreads();
  float inv = s_misc[0];

  // ---- pass 2: weighted sum over the warp's 128-col slice ----
  int col = wp * 128 + lane * 4;
  const float* __restrict__ bp = base + col;
  float4 a0 = make_float4(0.f, 0.f, 0.f, 0.f), a1 = a0, a2 = a0, a3 = a0;
  int w = 0;
  for (; w + 3 < len; w += 4) {
    float e0 = s_wt[w], e1 = s_wt[w + 1], e2 = s_wt[w + 2], e3 = s_wt[w + 3];
    float4 r0 = *reinterpret_cast<const float4*>(bp + (long)w * D);
    float4 r1 = *reinterpret_cast<const float4*>(bp + (long)(w + 1) * D);
    float4 r2 = *reinterpret_cast<const float4*>(bp + (long)(w + 2) * D);
    float4 r3 = *reinterpret_cast<const float4*>(bp + (long)(w + 3) * D);
    a0.x = fmaf(e0, r0.x, a0.x); a0.y = fmaf(e0, r0.y, a0.y);
    a0.z = fmaf(e0, r0.z, a0.z); a0.w = fmaf(e0, r0.w, a0.w);
    a1.x = fmaf(e1, r1.x, a1.x); a1.y = fmaf(e1, r1.y, a1.y);
    a1.z = fmaf(e1, r1.z, a1.z); a1.w = fmaf(e1, r1.w, a1.w);
    a2.x = fmaf(e2, r2.x, a2.x); a2.y = fmaf(e2, r2.y, a2.y);
    a2.z = fmaf(e2, r2.z, a2.z); a2.w = fmaf(e2, r2.w, a2.w);
    a3.x = fmaf(e3, r3.x, a3.x); a3.y = fmaf(e3, r3.y, a3.y);
    a3.z = fmaf(e3, r3.z, a3.z); a3.w = fmaf(e3, r3.w, a3.w);
  }
  for (; w < len; w++) {
    float e0 = s_wt[w];
    float4 r0 = *reinterpret_cast<const float4*>(bp + (long)w * D);
    a0.x = fmaf(e0, r0.x, a0.x); a0.y = fmaf(e0, r0.y, a0.y);
    a0.z = fmaf(e0, r0.z, a0.z); a0.w = fmaf(e0, r0.w, a0.w);
  }
  float4 cw = make_float4((a0.x + a1.x + a2.x + a3.x) * inv,
                          (a0.y + a1.y + a2.y + a3.y) * inv,
                          (a0.z + a1.z + a2.z + a3.z) * inv,
                          (a0.w + a1.w + a2.w + a3.w) * inv);
  *reinterpret_cast<float4*>(g_cw + (b * T + t) * D + col) = cw;

  // ---- turn score: q_t . cw ----
  float4 qt = *reinterpret_cast<const float4*>(g_q + (B + b) * D + col);
  float tp = fmaf(qt.x, cw.x, fmaf(qt.y, cw.y, fmaf(qt.z, cw.z, qt.w * cw.w)));
#pragma unroll
  for (int off = 16; off; off >>= 1) tp += __shfl_down_sync(0xffffffffu, tp, off);
  if (lane == 0) s_misc[4 + wp] = tp;
  __syncthreads();
  if (tid == 0) {
    float v = 0.f;
#pragma unroll
    for (int k = 0; k < 8; k++) v += s_misc[4 + k];
    g_ts[b * T + t] = v;
  }
}

// ---------------------------------------------------------------------------
// Kernel 4: turn softmax + combine. grid = (8 col-chunks, B) = 128 CTAs,
// 256 threads: tid -> (turn-group tg = tid>>5 of 4 turns, float4 col c).
// Masked turns have weight exactly 0 and zero g_cw rows.
// ---------------------------------------------------------------------------
__global__ __launch_bounds__(256) void combine_kernel(
    const int* __restrict__ turns, float* __restrict__ out) {
  int b = blockIdx.y;
  int chunk = blockIdx.x;  // 128 cols = 32 float4
  int nt = turns[b];
  int tid = threadIdx.x;
  __shared__ float attw[T];
  __shared__ __align__(16) float s_red[8][128];
  if (tid < 32) {  // T == 32
    float s = (tid < nt) ? g_ts[b * T + tid] : -CUDART_INF_F;
    float mx = s;
#pragma unroll
    for (int off = 16; off; off >>= 1)
      mx = fmaxf(mx, __shfl_xor_sync(0xffffffffu, mx, off));
    float e = (tid < nt) ? __expf(s - mx) : 0.f;
    float sm = e;
#pragma unroll
    for (int off = 16; off; off >>= 1)
      sm += __shfl_xor_sync(0xffffffffu, sm, off);
    attw[tid] = e / sm;
  }
  __syncthreads();

  int c = tid & 31;   // float4 index within the 128-col chunk
  int tg = tid >> 5;  // 0..7 -> turns tg*4 .. tg*4+3
  int c4 = chunk * 128 + c * 4;
  float4 acc = make_float4(0.f, 0.f, 0.f, 0.f);
#pragma unroll
  for (int i = 0; i < 4; i++) {
    int t = tg * 4 + i;
    float a = attw[t];
    float4 cw = *reinterpret_cast<const float4*>(g_cw + (b * T + t) * D + c4);
    acc.x = fmaf(a, cw.x, acc.x);
    acc.y = fmaf(a, cw.y, acc.y);
    acc.z = fmaf(a, cw.z, acc.z);
    acc.w = fmaf(a, cw.w, acc.w);
  }
  *reinterpret_cast<float4*>(&s_red[tg][c * 4]) = acc;
  __syncthreads();
  if (tid < 32) {
    float4 o = make_float4(0.f, 0.f, 0.f, 0.f);
#pragma unroll
    for (int k = 0; k < 8; k++) {
      float4 v = *reinterpret_cast<const float4*>(&s_red[k][tid * 4]);
      o.x += v.x; o.y += v.y; o.z += v.z; o.w += v.w;
    }
    *reinterpret_cast<float4*>(out + b * D + chunk * 128 + tid * 4) = o;
  }
}

// ---------------------------------------------------------------------------
extern "C" void kernel_launch(void* const* d_in, const int* in_sizes, int n_in,
                              void* d_out, int out_size) {
  const float *src = nullptr, *bank = nullptr, *Wword = nullptr, *Wturn = nullptr;
  const int *lens = nullptr, *turns = nullptr;
  for (int i = 0; i < n_in; i++) {
    switch (in_sizes[i]) {
      case B * D:            src  = (const float*)d_in[i]; break;
      case B * T * WW * D:   bank = (const float*)d_in[i]; break;
      case B * T:            lens = (const int*)d_in[i];   break;
      case B:                turns = (const int*)d_in[i];  break;
      case D * D:
        if (!Wword) Wword = (const float*)d_in[i];
        else        Wturn = (const float*)d_in[i];
        break;
      default: break;
    }
  }
  proj_part_kernel<<<dim3(NDBLK, 1, 2), 256>>>(src, Wword, Wturn);
  reduce_q_kernel<<<32, 256>>>();
  attn_kernel<<<dim3(T, B), 256>>>(bank, lens, turns);
  combine_kernel<<<dim3(8, B), 256>>>(turns, (float*)d_out);
}

// round 6
// speedup vs baseline: 1.3679x; 1.3679x over previous
#include <cuda_runtime.h>
#include <math_constants.h>

#define B 16
#define T 32
#define WW 128
#define D 1024
#define NDBLK 32            // d-chunks for projection partials
#define DCHUNK (D / NDBLK)  // 32

// Scratch (no device allocation allowed). .bss is zero-initialized: masked-turn
// rows of g_cw are never written and stay exactly 0 across graph replays.
__device__ float g_part[2 * NDBLK * B * D];  // 4 MB
__device__ float g_q[2 * B * D];
__device__ float g_cw[B * T * D];
__device__ float g_ts[B * T];

// ---------------------------------------------------------------------------
// Kernel 1: partial projections q = source @ W (W stored [indim, outdim]).
// grid = (NDBLK, 1, 2 mats) = 64 CTAs, 256 threads. One CTA covers ALL 16
// batch rows -> W is read exactly once (8 MB total). [R4-measured]
// ---------------------------------------------------------------------------
__global__ __launch_bounds__(256) void proj_part_kernel(
    const float* __restrict__ src, const float* __restrict__ Wword,
    const float* __restrict__ Wturn) {
  int dblk = blockIdx.x;
  int mat = blockIdx.z;
  const float* __restrict__ Wm = mat ? Wturn : Wword;
  int c4 = threadIdx.x * 4;
  int d0 = dblk * DCHUNK;

  __shared__ float s_src[DCHUNK][B];
#pragma unroll
  for (int e = threadIdx.x; e < DCHUNK * B; e += 256) {
    int dl = e >> 4, bb = e & 15;
    s_src[dl][bb] = src[bb * D + d0 + dl];
  }
  __syncthreads();

  float4 acc[B];
#pragma unroll
  for (int bb = 0; bb < B; bb++) acc[bb] = make_float4(0.f, 0.f, 0.f, 0.f);

#pragma unroll
  for (int dl = 0; dl < DCHUNK; dl++) {
    float4 wv = *reinterpret_cast<const float4*>(&Wm[(d0 + dl) * D + c4]);
#pragma unroll
    for (int bb = 0; bb < B; bb++) {
      float s = s_src[dl][bb];
      acc[bb].x = fmaf(s, wv.x, acc[bb].x);
      acc[bb].y = fmaf(s, wv.y, acc[bb].y);
      acc[bb].z = fmaf(s, wv.z, acc[bb].z);
      acc[bb].w = fmaf(s, wv.w, acc[bb].w);
    }
  }

#pragma unroll
  for (int bb = 0; bb < B; bb++) {
    float* outp = g_part + ((long)(mat * NDBLK + dblk) * B + bb) * D + c4;
    *reinterpret_cast<float4*>(outp) = acc[bb];
  }
}

// ---------------------------------------------------------------------------
// Kernel 2: reduce NDBLK partials -> g_q[2][B][D]. grid = 128 x 256.
// One scalar output per thread, 32 independent coalesced 4B loads in flight.
// ---------------------------------------------------------------------------
__global__ __launch_bounds__(256) void reduce_q_kernel() {
  int idx = blockIdx.x * 256 + threadIdx.x;  // 0..32767 over [2][16][1024]
  int mat = idx >> 14;
  int b = (idx >> 10) & 15;
  int c = idx & 1023;
  const float* bp = g_part + ((long)mat * NDBLK * B + b) * D + c;
  float s0 = 0.f, s1 = 0.f, s2 = 0.f, s3 = 0.f;
#pragma unroll
  for (int j = 0; j < NDBLK; j += 4) {
    s0 += bp[(long)(j + 0) * B * D];
    s1 += bp[(long)(j + 1) * B * D];
    s2 += bp[(long)(j + 2) * B * D];
    s3 += bp[(long)(j + 3) * B * D];
  }
  g_q[(mat * B + b) * D + c] = (s0 + s1) + (s2 + s3);
}

// ---------------------------------------------------------------------------
// Kernel 3: per-(b,t) word attention [R3-measured, verbatim structure].
// 256 threads, 8 warps; warp-private online softmax, no barriers in the main
// loop. Warp wp handles rows wp, wp+8, ... (2 per iter); each lane owns 8
// strided float4 column segments (full D per warp). Single end merge.
// ---------------------------------------------------------------------------
__global__ __launch_bounds__(256) void attn_kernel(
    const float* __restrict__ bank, const int* __restrict__ lens,
    const int* __restrict__ turns) {
  int t = blockIdx.x, b = blockIdx.y;
  if (t >= turns[b]) return;  // masked turn: contributes exactly 0 downstream
  int len = lens[b * T + t];
  int tid = threadIdx.x, wp = tid >> 5, lane = tid & 31;

  float4 qw[8];
#pragma unroll
  for (int j = 0; j < 8; j++)
    qw[j] = *reinterpret_cast<const float4*>(g_q + b * D + j * 128 + lane * 4);

  const float* __restrict__ base = bank + (long)(b * T + t) * WW * D;

  float m = -CUDART_INF_F, ssum = 0.f;
  float4 acc[8];
#pragma unroll
  for (int j = 0; j < 8; j++) acc[j] = make_float4(0.f, 0.f, 0.f, 0.f);

  int w = wp;
#pragma unroll 1
  for (; w + 8 < len; w += 16) {  // two rows per iteration: w, w+8
    float4 r0[8], r1[8];
#pragma unroll
    for (int j = 0; j < 8; j++)
      r0[j] = *reinterpret_cast<const float4*>(base + w * D + j * 128 + lane * 4);
#pragma unroll
    for (int j = 0; j < 8; j++)
      r1[j] = *reinterpret_cast<const float4*>(base + (w + 8) * D + j * 128 + lane * 4);

    float p0 = 0.f, p1 = 0.f;
#pragma unroll
    for (int j = 0; j < 8; j++) {
      p0 = fmaf(qw[j].x, r0[j].x, fmaf(qw[j].y, r0[j].y,
           fmaf(qw[j].z, r0[j].z, fmaf(qw[j].w, r0[j].w, p0))));
      p1 = fmaf(qw[j].x, r1[j].x, fmaf(qw[j].y, r1[j].y,
           fmaf(qw[j].z, r1[j].z, fmaf(qw[j].w, r1[j].w, p1))));
    }
#pragma unroll
    for (int off = 16; off; off >>= 1) {
      p0 += __shfl_xor_sync(0xffffffffu, p0, off);
      p1 += __shfl_xor_sync(0xffffffffu, p1, off);
    }
    float mnew = fmaxf(m, fmaxf(p0, p1));
    float sc = __expf(m - mnew);        // 0 on first iteration (m = -inf)
    float e0 = __expf(p0 - mnew);
    float e1 = __expf(p1 - mnew);
    ssum = fmaf(ssum, sc, e0 + e1);
    m = mnew;
#pragma unroll
    for (int j = 0; j < 8; j++) {
      acc[j].x = fmaf(e1, r1[j].x, fmaf(e0, r0[j].x, acc[j].x * sc));
      acc[j].y = fmaf(e1, r1[j].y, fmaf(e0, r0[j].y, acc[j].y * sc));
      acc[j].z = fmaf(e1, r1[j].z, fmaf(e0, r0[j].z, acc[j].z * sc));
      acc[j].w = fmaf(e1, r1[j].w, fmaf(e0, r0[j].w, acc[j].w * sc));
    }
  }
  if (w < len) {  // tail row
    float4 r0[8];
#pragma unroll
    for (int j = 0; j < 8; j++)
      r0[j] = *reinterpret_cast<const float4*>(base + w * D + j * 128 + lane * 4);
    float p0 = 0.f;
#pragma unroll
    for (int j = 0; j < 8; j++)
      p0 = fmaf(qw[j].x, r0[j].x, fmaf(qw[j].y, r0[j].y,
           fmaf(qw[j].z, r0[j].z, fmaf(qw[j].w, r0[j].w, p0))));
#pragma unroll
    for (int off = 16; off; off >>= 1) p0 += __shfl_xor_sync(0xffffffffu, p0, off);
    float mnew = fmaxf(m, p0);
    float sc = __expf(m - mnew);
    float e0 = __expf(p0 - mnew);
    ssum = fmaf(ssum, sc, e0);
    m = mnew;
#pragma unroll
    for (int j = 0; j < 8; j++) {
      acc[j].x = fmaf(e0, r0[j].x, acc[j].x * sc);
      acc[j].y = fmaf(e0, r0[j].y, acc[j].y * sc);
      acc[j].z = fmaf(e0, r0[j].z, acc[j].z * sc);
      acc[j].w = fmaf(e0, r0[j].w, acc[j].w * sc);
    }
  }

  // ---- merge 8 warp-private (m, ssum, acc) states ----
  __shared__ float s_ms[8][2];
  __shared__ __align__(16) float s_acc[8][D];  // 32 KB
  if (lane == 0) { s_ms[wp][0] = m; s_ms[wp][1] = ssum; }
  __syncthreads();
  float M = -CUDART_INF_F;
#pragma unroll
  for (int k = 0; k < 8; k++) M = fmaxf(M, s_ms[k][0]);
  float S = 0.f;
#pragma unroll
  for (int k = 0; k < 8; k++) S += s_ms[k][1] * __expf(s_ms[k][0] - M);
  float wt = __expf(m - M);  // 0 for warps that saw no rows (m = -inf)
#pragma unroll
  for (int j = 0; j < 8; j++) {
    float4 v = make_float4(acc[j].x * wt, acc[j].y * wt, acc[j].z * wt, acc[j].w * wt);
    *reinterpret_cast<float4*>(&s_acc[wp][j * 128 + lane * 4]) = v;
  }
  __syncthreads();

  int c4 = tid * 4;
  float4 sum = make_float4(0.f, 0.f, 0.f, 0.f);
#pragma unroll
  for (int k = 0; k < 8; k++) {
    float4 v = *reinterpret_cast<const float4*>(&s_acc[k][c4]);
    sum.x += v.x; sum.y += v.y; sum.z += v.z; sum.w += v.w;
  }
  float inv = 1.f / S;
  float4 cw = make_float4(sum.x * inv, sum.y * inv, sum.z * inv, sum.w * inv);
  *reinterpret_cast<float4*>(g_cw + (b * T + t) * D + c4) = cw;

  // turn score: q_t . cw (block reduce)
  float4 qt = *reinterpret_cast<const float4*>(g_q + (B + b) * D + c4);
  float tp = fmaf(qt.x, cw.x, fmaf(qt.y, cw.y, fmaf(qt.z, cw.z, qt.w * cw.w)));
#pragma unroll
  for (int off = 16; off; off >>= 1) tp += __shfl_down_sync(0xffffffffu, tp, off);
  if (lane == 0) s_ms[wp][0] = tp;  // all s_ms reads completed before 2nd barrier
  __syncthreads();
  if (tid == 0) {
    float v = 0.f;
#pragma unroll
    for (int k = 0; k < 8; k++) v += s_ms[k][0];
    g_ts[b * T + t] = v;
  }
}

// ---------------------------------------------------------------------------
// Kernel 4: turn softmax + combine [R5-measured]. grid = (8 col-chunks, B)
// = 128 CTAs, 256 threads: tid -> (turn-group tg = tid>>5 of 4 turns, col c).
// Masked turns have weight exactly 0 and zero g_cw rows.
// ---------------------------------------------------------------------------
__global__ __launch_bounds__(256) void combine_kernel(
    const int* __restrict__ turns, float* __restrict__ out) {
  int b = blockIdx.y;
  int chunk = blockIdx.x;  // 128 cols = 32 float4
  int nt = turns[b];
  int tid = threadIdx.x;
  __shared__ float attw[T];
  __shared__ __align__(16) float s_red[8][128];
  if (tid < 32) {  // T == 32
    float s = (tid < nt) ? g_ts[b * T + tid] : -CUDART_INF_F;
    float mx = s;
#pragma unroll
    for (int off = 16; off; off >>= 1)
      mx = fmaxf(mx, __shfl_xor_sync(0xffffffffu, mx, off));
    float e = (tid < nt) ? __expf(s - mx) : 0.f;
    float sm = e;
#pragma unroll
    for (int off = 16; off; off >>= 1)
      sm += __shfl_xor_sync(0xffffffffu, sm, off);
    attw[tid] = e / sm;
  }
  __syncthreads();

  int c = tid & 31;   // float4 index within the 128-col chunk
  int tg = tid >> 5;  // 0..7 -> turns tg*4 .. tg*4+3
  int c4 = chunk * 128 + c * 4;
  float4 acc = make_float4(0.f, 0.f, 0.f, 0.f);
#pragma unroll
  for (int i = 0; i < 4; i++) {
    int t = tg * 4 + i;
    float a = attw[t];
    float4 cw = *reinterpret_cast<const float4*>(g_cw + (b * T + t) * D + c4);
    acc.x = fmaf(a, cw.x, acc.x);
    acc.y = fmaf(a, cw.y, acc.y);
    acc.z = fmaf(a, cw.z, acc.z);
    acc.w = fmaf(a, cw.w, acc.w);
  }
  *reinterpret_cast<float4*>(&s_red[tg][c * 4]) = acc;
  __syncthreads();
  if (tid < 32) {
    float4 o = make_float4(0.f, 0.f, 0.f, 0.f);
#pragma unroll
    for (int k = 0; k < 8; k++) {
      float4 v = *reinterpret_cast<const float4*>(&s_red[k][tid * 4]);
      o.x += v.x; o.y += v.y; o.z += v.z; o.w += v.w;
    }
    *reinterpret_cast<float4*>(out + b * D + chunk * 128 + tid * 4) = o;
  }
}

// ---------------------------------------------------------------------------
extern "C" void kernel_launch(void* const* d_in, const int* in_sizes, int n_in,
                              void* d_out, int out_size) {
  const float *src = nullptr, *bank = nullptr, *Wword = nullptr, *Wturn = nullptr;
  const int *lens = nullptr, *turns = nullptr;
  for (int i = 0; i < n_in; i++) {
    switch (in_sizes[i]) {
      case B * D:            src  = (const float*)d_in[i]; break;
      case B * T * WW * D:   bank = (const float*)d_in[i]; break;
      case B * T:            lens = (const int*)d_in[i];   break;
      case B:                turns = (const int*)d_in[i];  break;
      case D * D:
        if (!Wword) Wword = (const float*)d_in[i];
        else        Wturn = (const float*)d_in[i];
        break;
      default: break;
    }
  }
  proj_part_kernel<<<dim3(NDBLK, 1, 2), 256>>>(src, Wword, Wturn);
  reduce_q_kernel<<<128, 256>>>();
  attn_kernel<<<dim3(T, B), 256>>>(bank, lens, turns);
  combine_kernel<<<dim3(8, B), 256>>>(turns, (float*)d_out);
}

// round 7
// speedup vs baseline: 1.3707x; 1.0020x over previous
#include <cuda_runtime.h>
#include <math_constants.h>

#define B 16
#define T 32
#define WW 128
#define D 1024
#define NDBLK 32            // d-chunks for projection partials
#define DCHUNK (D / NDBLK)  // 32

// Scratch (no device allocation allowed). .bss is zero-initialized: masked-turn
// rows of g_cw are never written and stay exactly 0 across graph replays.
__device__ float g_part[2 * NDBLK * B * D];  // 4 MB
__device__ float g_q[2 * B * D];
__device__ float g_cw[B * T * D];
__device__ float g_ts[B * T];
__device__ int g_cnt[B];  // per-batch completion tickets (reset each call)

// ---------------------------------------------------------------------------
// Kernel 1: partial projections q = source @ W (W stored [indim, outdim]).
// grid = (NDBLK, 1, 2 mats) = 64 CTAs, 256 threads; W read exactly once.
// ---------------------------------------------------------------------------
__global__ __launch_bounds__(256) void proj_part_kernel(
    const float* __restrict__ src, const float* __restrict__ Wword,
    const float* __restrict__ Wturn) {
  int dblk = blockIdx.x;
  int mat = blockIdx.z;
  const float* __restrict__ Wm = mat ? Wturn : Wword;
  int c4 = threadIdx.x * 4;
  int d0 = dblk * DCHUNK;

  __shared__ float s_src[DCHUNK][B];
#pragma unroll
  for (int e = threadIdx.x; e < DCHUNK * B; e += 256) {
    int dl = e >> 4, bb = e & 15;
    s_src[dl][bb] = src[bb * D + d0 + dl];
  }
  __syncthreads();

  float4 acc[B];
#pragma unroll
  for (int bb = 0; bb < B; bb++) acc[bb] = make_float4(0.f, 0.f, 0.f, 0.f);

#pragma unroll
  for (int dl = 0; dl < DCHUNK; dl++) {
    float4 wv = *reinterpret_cast<const float4*>(&Wm[(d0 + dl) * D + c4]);
#pragma unroll
    for (int bb = 0; bb < B; bb++) {
      float s = s_src[dl][bb];
      acc[bb].x = fmaf(s, wv.x, acc[bb].x);
      acc[bb].y = fmaf(s, wv.y, acc[bb].y);
      acc[bb].z = fmaf(s, wv.z, acc[bb].z);
      acc[bb].w = fmaf(s, wv.w, acc[bb].w);
    }
  }

#pragma unroll
  for (int bb = 0; bb < B; bb++) {
    float* outp = g_part + ((long)(mat * NDBLK + dblk) * B + bb) * D + c4;
    *reinterpret_cast<float4*>(outp) = acc[bb];
  }
}

// ---------------------------------------------------------------------------
// Kernel 2: reduce NDBLK partials -> g_q[2][B][D]; also resets g_cnt (stream-
// ordered before attn, so replays are deterministic). grid = 128 x 256.
// ---------------------------------------------------------------------------
__global__ __launch_bounds__(256) void reduce_q_kernel() {
  if (blockIdx.x == 0 && threadIdx.x < B) g_cnt[threadIdx.x] = 0;
  int idx = blockIdx.x * 256 + threadIdx.x;  // 0..32767 over [2][16][1024]
  int mat = idx >> 14;
  int b = (idx >> 10) & 15;
  int c = idx & 1023;
  const float* bp = g_part + ((long)mat * NDBLK * B + b) * D + c;
  float s0 = 0.f, s1 = 0.f, s2 = 0.f, s3 = 0.f;
#pragma unroll
  for (int j = 0; j < NDBLK; j += 4) {
    s0 += bp[(long)(j + 0) * B * D];
    s1 += bp[(long)(j + 1) * B * D];
    s2 += bp[(long)(j + 2) * B * D];
    s3 += bp[(long)(j + 3) * B * D];
  }
  g_q[(mat * B + b) * D + c] = (s0 + s1) + (s2 + s3);
}

// ---------------------------------------------------------------------------
// Kernel 3: per-(b,t) word attention + FUSED turn combine.
// 256 threads, 8 warps, 2 CTAs/SM (1 row/iter keeps regs ~110).
// Warp wp handles rows wp, wp+8, ...; lane owns 8 strided float4 segments.
// After writing cw/ts, CTAs take a per-batch ticket; the LAST CTA of batch b
// performs the turn softmax + weighted combine for b (L2-hot data).
// ---------------------------------------------------------------------------
__global__ __launch_bounds__(256, 2) void attn_kernel(
    const float* __restrict__ bank, const int* __restrict__ lens,
    const int* __restrict__ turns, float* __restrict__ out) {
  int t = blockIdx.x, b = blockIdx.y;
  int nt = turns[b];
  if (t >= nt) return;  // masked turn: contributes exactly 0 downstream
  int len = lens[b * T + t];
  int tid = threadIdx.x, wp = tid >> 5, lane = tid & 31;

  float4 qw[8];
#pragma unroll
  for (int j = 0; j < 8; j++)
    qw[j] = *reinterpret_cast<const float4*>(g_q + b * D + j * 128 + lane * 4);

  const float* __restrict__ base = bank + (long)(b * T + t) * WW * D;

  float m = -CUDART_INF_F, ssum = 0.f;
  float4 acc[8];
#pragma unroll
  for (int j = 0; j < 8; j++) acc[j] = make_float4(0.f, 0.f, 0.f, 0.f);

#pragma unroll 1
  for (int w = wp; w < len; w += 8) {
    float4 r[8];
#pragma unroll
    for (int j = 0; j < 8; j++)
      r[j] = *reinterpret_cast<const float4*>(base + w * D + j * 128 + lane * 4);
    float p = 0.f;
#pragma unroll
    for (int j = 0; j < 8; j++)
      p = fmaf(qw[j].x, r[j].x, fmaf(qw[j].y, r[j].y,
          fmaf(qw[j].z, r[j].z, fmaf(qw[j].w, r[j].w, p))));
#pragma unroll
    for (int off = 16; off; off >>= 1) p += __shfl_xor_sync(0xffffffffu, p, off);
    float mnew = fmaxf(m, p);
    float sc = __expf(m - mnew);  // 0 on first row (m = -inf)
    float e = __expf(p - mnew);
    ssum = fmaf(ssum, sc, e);
    m = mnew;
#pragma unroll
    for (int j = 0; j < 8; j++) {
      acc[j].x = fmaf(e, r[j].x, acc[j].x * sc);
      acc[j].y = fmaf(e, r[j].y, acc[j].y * sc);
      acc[j].z = fmaf(e, r[j].z, acc[j].z * sc);
      acc[j].w = fmaf(e, r[j].w, acc[j].w * sc);
    }
  }

  // ---- merge 8 warp-private (m, ssum, acc) states ----
  __shared__ float s_ms[8][2];
  __shared__ __align__(16) float s_acc[8][D];  // 32 KB (2 CTAs/SM -> 64 KB)
  if (lane == 0) { s_ms[wp][0] = m; s_ms[wp][1] = ssum; }
  __syncthreads();
  float M = -CUDART_INF_F;
#pragma unroll
  for (int k = 0; k < 8; k++) M = fmaxf(M, s_ms[k][0]);
  float S = 0.f;
#pragma unroll
  for (int k = 0; k < 8; k++) S += s_ms[k][1] * __expf(s_ms[k][0] - M);
  float wt = __expf(m - M);  // 0 for warps that saw no rows (m = -inf)
#pragma unroll
  for (int j = 0; j < 8; j++) {
    float4 v = make_float4(acc[j].x * wt, acc[j].y * wt, acc[j].z * wt, acc[j].w * wt);
    *reinterpret_cast<float4*>(&s_acc[wp][j * 128 + lane * 4]) = v;
  }
  __syncthreads();

  int c4 = tid * 4;
  float4 sum = make_float4(0.f, 0.f, 0.f, 0.f);
#pragma unroll
  for (int k = 0; k < 8; k++) {
    float4 v = *reinterpret_cast<const float4*>(&s_acc[k][c4]);
    sum.x += v.x; sum.y += v.y; sum.z += v.z; sum.w += v.w;
  }
  float inv = 1.f / S;
  float4 cw = make_float4(sum.x * inv, sum.y * inv, sum.z * inv, sum.w * inv);
  *reinterpret_cast<float4*>(g_cw + (b * T + t) * D + c4) = cw;

  // turn score: q_t . cw (block reduce)
  float4 qt = *reinterpret_cast<const float4*>(g_q + (B + b) * D + c4);
  float tp = fmaf(qt.x, cw.x, fmaf(qt.y, cw.y, fmaf(qt.z, cw.z, qt.w * cw.w)));
#pragma unroll
  for (int off = 16; off; off >>= 1) tp += __shfl_down_sync(0xffffffffu, tp, off);
  if (lane == 0) s_ms[wp][0] = tp;
  __syncthreads();
  if (tid == 0) {
    float v = 0.f;
#pragma unroll
    for (int k = 0; k < 8; k++) v += s_ms[k][0];
    g_ts[b * T + t] = v;
  }

  // ---- ticket: last CTA of batch b performs the turn combine ----
  __shared__ int s_last;
  __threadfence();  // release our g_cw/g_ts writes
  __syncthreads();  // all threads' stores issued before the ticket
  if (tid == 0) s_last = (atomicAdd(&g_cnt[b], 1) == nt - 1);
  __syncthreads();
  if (!s_last) return;
  __threadfence();  // acquire: observe all other CTAs' writes for batch b

  __shared__ float attw[T];
  if (tid < 32) {  // T == 32; masked turns get weight exactly 0
    float s = (tid < nt) ? g_ts[b * T + tid] : -CUDART_INF_F;
    float mx = s;
#pragma unroll
    for (int off = 16; off; off >>= 1)
      mx = fmaxf(mx, __shfl_xor_sync(0xffffffffu, mx, off));
    float e = (tid < nt) ? __expf(s - mx) : 0.f;
    float sm = e;
#pragma unroll
    for (int off = 16; off; off >>= 1)
      sm += __shfl_xor_sync(0xffffffffu, sm, off);
    attw[tid] = e / sm;
  }
  __syncthreads();

  // weighted combine over 32 turns (masked rows of g_cw are exactly 0)
  float4 o0 = make_float4(0.f, 0.f, 0.f, 0.f), o1 = o0, o2 = o0, o3 = o0;
  const float* cwb = g_cw + (long)b * T * D + c4;
#pragma unroll
  for (int tt = 0; tt < T; tt += 4) {
    float a0 = attw[tt], a1 = attw[tt + 1], a2 = attw[tt + 2], a3 = attw[tt + 3];
    float4 v0 = *reinterpret_cast<const float4*>(cwb + (long)tt * D);
    float4 v1 = *reinterpret_cast<const float4*>(cwb + (long)(tt + 1) * D);
    float4 v2 = *reinterpret_cast<const float4*>(cwb + (long)(tt + 2) * D);
    float4 v3 = *reinterpret_cast<const float4*>(cwb + (long)(tt + 3) * D);
    o0.x = fmaf(a0, v0.x, o0.x); o0.y = fmaf(a0, v0.y, o0.y);
    o0.z = fmaf(a0, v0.z, o0.z); o0.w = fmaf(a0, v0.w, o0.w);
    o1.x = fmaf(a1, v1.x, o1.x); o1.y = fmaf(a1, v1.y, o1.y);
    o1.z = fmaf(a1, v1.z, o1.z); o1.w = fmaf(a1, v1.w, o1.w);
    o2.x = fmaf(a2, v2.x, o2.x); o2.y = fmaf(a2, v2.y, o2.y);
    o2.z = fmaf(a2, v2.z, o2.z); o2.w = fmaf(a2, v2.w, o2.w);
    o3.x = fmaf(a3, v3.x, o3.x); o3.y = fmaf(a3, v3.y, o3.y);
    o3.z = fmaf(a3, v3.z, o3.z); o3.w = fmaf(a3, v3.w, o3.w);
  }
  float4 o = make_float4(o0.x + o1.x + o2.x + o3.x, o0.y + o1.y + o2.y + o3.y,
                         o0.z + o1.z + o2.z + o3.z, o0.w + o1.w + o2.w + o3.w);
  *reinterpret_cast<float4*>(out + b * D + c4) = o;
}

// ---------------------------------------------------------------------------
extern "C" void kernel_launch(void* const* d_in, const int* in_sizes, int n_in,
                              void* d_out, int out_size) {
  const float *src = nullptr, *bank = nullptr, *Wword = nullptr, *Wturn = nullptr;
  const int *lens = nullptr, *turns = nullptr;
  for (int i = 0; i < n_in; i++) {
    switch (in_sizes[i]) {
      case B * D:            src  = (const float*)d_in[i]; break;
      case B * T * WW * D:   bank = (const float*)d_in[i]; break;
      case B * T:            lens = (const int*)d_in[i];   break;
      case B:                turns = (const int*)d_in[i];  break;
      case D * D:
        if (!Wword) Wword = (const float*)d_in[i];
        else        Wturn = (const float*)d_in[i];
        break;
      default: break;
    }
  }
  proj_part_kernel<<<dim3(NDBLK, 1, 2), 256>>>(src, Wword, Wturn);
  reduce_q_kernel<<<128, 256>>>();
  attn_kernel<<<dim3(T, B), 256>>>(bank, lens, turns, (float*)d_out);
}

// round 8
// speedup vs baseline: 1.3791x; 1.0061x over previous
#include <cuda_runtime.h>
#include <math_constants.h>

#define B 16
#define T 32
#define WW 128
#define D 1024
#define NDBLK 64            // d-chunks for projection partials
#define DCHUNK (D / NDBLK)  // 16

// Scratch (no device allocation allowed). .bss is zero-initialized: masked-turn
// rows of g_cw are never written and stay exactly 0 across graph replays.
__device__ float g_part[2 * NDBLK * B * D];  // 8 MB
__device__ float g_q[2 * B * D];
__device__ float g_cw[B * T * D];
__device__ float g_ts[B * T];
__device__ int g_cnt[B];  // per-batch completion tickets (reset each call)

// ---------------------------------------------------------------------------
// Kernel 1: partial projections q = source @ W (W stored [indim, outdim]).
// grid = (NDBLK, 1, 2 mats) = 128 CTAs (one full wave; FMA-issue time/SM
// halved vs 64 CTAs), 256 threads; W read exactly once (8 MB).
// ---------------------------------------------------------------------------
__global__ __launch_bounds__(256) void proj_part_kernel(
    const float* __restrict__ src, const float* __restrict__ Wword,
    const float* __restrict__ Wturn) {
  int dblk = blockIdx.x;
  int mat = blockIdx.z;
  const float* __restrict__ Wm = mat ? Wturn : Wword;
  int c4 = threadIdx.x * 4;
  int d0 = dblk * DCHUNK;

  __shared__ float s_src[DCHUNK][B];
  if (threadIdx.x < DCHUNK * B) {  // 16*16 = 256
    int dl = threadIdx.x >> 4, bb = threadIdx.x & 15;
    s_src[dl][bb] = src[bb * D + d0 + dl];
  }
  __syncthreads();

  float4 acc[B];
#pragma unroll
  for (int bb = 0; bb < B; bb++) acc[bb] = make_float4(0.f, 0.f, 0.f, 0.f);

#pragma unroll
  for (int dl = 0; dl < DCHUNK; dl++) {
    float4 wv = *reinterpret_cast<const float4*>(&Wm[(d0 + dl) * D + c4]);
#pragma unroll
    for (int bb = 0; bb < B; bb++) {
      float s = s_src[dl][bb];
      acc[bb].x = fmaf(s, wv.x, acc[bb].x);
      acc[bb].y = fmaf(s, wv.y, acc[bb].y);
      acc[bb].z = fmaf(s, wv.z, acc[bb].z);
      acc[bb].w = fmaf(s, wv.w, acc[bb].w);
    }
  }

#pragma unroll
  for (int bb = 0; bb < B; bb++) {
    float* outp = g_part + ((long)(mat * NDBLK + dblk) * B + bb) * D + c4;
    *reinterpret_cast<float4*>(outp) = acc[bb];
  }
}

// ---------------------------------------------------------------------------
// Kernel 2: reduce NDBLK partials -> g_q[2][B][D]; also resets g_cnt (stream-
// ordered before attn -> deterministic graph replays). grid = 128 x 256.
// ---------------------------------------------------------------------------
__global__ __launch_bounds__(256) void reduce_q_kernel() {
  if (blockIdx.x == 0 && threadIdx.x < B) g_cnt[threadIdx.x] = 0;
  int idx = blockIdx.x * 256 + threadIdx.x;  // 0..32767 over [2][16][1024]
  int mat = idx >> 14;
  int b = (idx >> 10) & 15;
  int c = idx & 1023;
  const float* bp = g_part + ((long)mat * NDBLK * B + b) * D + c;
  float s0 = 0.f, s1 = 0.f, s2 = 0.f, s3 = 0.f;
#pragma unroll
  for (int j = 0; j < NDBLK; j += 4) {
    s0 += bp[(long)(j + 0) * B * D];
    s1 += bp[(long)(j + 1) * B * D];
    s2 += bp[(long)(j + 2) * B * D];
    s3 += bp[(long)(j + 3) * B * D];
  }
  g_q[(mat * B + b) * D + c] = (s0 + s1) + (s2 + s3);
}

// ---------------------------------------------------------------------------
// Kernel 3: per-(b,t) word attention [R6-measured 2-row/iter body] + fused
// turn combine via per-batch ticket (last CTA of batch b does the combine).
// 256 threads, 8 warps; warp-private online softmax, no mainloop barriers.
// ---------------------------------------------------------------------------
__global__ __launch_bounds__(256) void attn_kernel(
    const float* __restrict__ bank, const int* __restrict__ lens,
    const int* __restrict__ turns, float* __restrict__ out) {
  int t = blockIdx.x, b = blockIdx.y;
  int nt = turns[b];
  if (t >= nt) return;  // masked turn: contributes exactly 0 downstream
  int len = lens[b * T + t];
  int tid = threadIdx.x, wp = tid >> 5, lane = tid & 31;

  float4 qw[8];
#pragma unroll
  for (int j = 0; j < 8; j++)
    qw[j] = *reinterpret_cast<const float4*>(g_q + b * D + j * 128 + lane * 4);

  const float* __restrict__ base = bank + (long)(b * T + t) * WW * D;

  float m = -CUDART_INF_F, ssum = 0.f;
  float4 acc[8];
#pragma unroll
  for (int j = 0; j < 8; j++) acc[j] = make_float4(0.f, 0.f, 0.f, 0.f);

  int w = wp;
#pragma unroll 1
  for (; w + 8 < len; w += 16) {  // two rows per iteration: w, w+8
    float4 r0[8], r1[8];
#pragma unroll
    for (int j = 0; j < 8; j++)
      r0[j] = *reinterpret_cast<const float4*>(base + w * D + j * 128 + lane * 4);
#pragma unroll
    for (int j = 0; j < 8; j++)
      r1[j] = *reinterpret_cast<const float4*>(base + (w + 8) * D + j * 128 + lane * 4);

    float p0 = 0.f, p1 = 0.f;
#pragma unroll
    for (int j = 0; j < 8; j++) {
      p0 = fmaf(qw[j].x, r0[j].x, fmaf(qw[j].y, r0[j].y,
           fmaf(qw[j].z, r0[j].z, fmaf(qw[j].w, r0[j].w, p0))));
      p1 = fmaf(qw[j].x, r1[j].x, fmaf(qw[j].y, r1[j].y,
           fmaf(qw[j].z, r1[j].z, fmaf(qw[j].w, r1[j].w, p1))));
    }
#pragma unroll
    for (int off = 16; off; off >>= 1) {
      p0 += __shfl_xor_sync(0xffffffffu, p0, off);
      p1 += __shfl_xor_sync(0xffffffffu, p1, off);
    }
    float mnew = fmaxf(m, fmaxf(p0, p1));
    float sc = __expf(m - mnew);        // 0 on first iteration (m = -inf)
    float e0 = __expf(p0 - mnew);
    float e1 = __expf(p1 - mnew);
    ssum = fmaf(ssum, sc, e0 + e1);
    m = mnew;
#pragma unroll
    for (int j = 0; j < 8; j++) {
      acc[j].x = fmaf(e1, r1[j].x, fmaf(e0, r0[j].x, acc[j].x * sc));
      acc[j].y = fmaf(e1, r1[j].y, fmaf(e0, r0[j].y, acc[j].y * sc));
      acc[j].z = fmaf(e1, r1[j].z, fmaf(e0, r0[j].z, acc[j].z * sc));
      acc[j].w = fmaf(e1, r1[j].w, fmaf(e0, r0[j].w, acc[j].w * sc));
    }
  }
  if (w < len) {  // tail row
    float4 r0[8];
#pragma unroll
    for (int j = 0; j < 8; j++)
      r0[j] = *reinterpret_cast<const float4*>(base + w * D + j * 128 + lane * 4);
    float p0 = 0.f;
#pragma unroll
    for (int j = 0; j < 8; j++)
      p0 = fmaf(qw[j].x, r0[j].x, fmaf(qw[j].y, r0[j].y,
           fmaf(qw[j].z, r0[j].z, fmaf(qw[j].w, r0[j].w, p0))));
#pragma unroll
    for (int off = 16; off; off >>= 1) p0 += __shfl_xor_sync(0xffffffffu, p0, off);
    float mnew = fmaxf(m, p0);
    float sc = __expf(m - mnew);
    float e0 = __expf(p0 - mnew);
    ssum = fmaf(ssum, sc, e0);
    m = mnew;
#pragma unroll
    for (int j = 0; j < 8; j++) {
      acc[j].x = fmaf(e0, r0[j].x, acc[j].x * sc);
      acc[j].y = fmaf(e0, r0[j].y, acc[j].y * sc);
      acc[j].z = fmaf(e0, r0[j].z, acc[j].z * sc);
      acc[j].w = fmaf(e0, r0[j].w, acc[j].w * sc);
    }
  }

  // ---- merge 8 warp-private (m, ssum, acc) states ----
  __shared__ float s_ms[8][2];
  __shared__ __align__(16) float s_acc[8][D];  // 32 KB
  if (lane == 0) { s_ms[wp][0] = m; s_ms[wp][1] = ssum; }
  __syncthreads();
  float M = -CUDART_INF_F;
#pragma unroll
  for (int k = 0; k < 8; k++) M = fmaxf(M, s_ms[k][0]);
  float S = 0.f;
#pragma unroll
  for (int k = 0; k < 8; k++) S += s_ms[k][1] * __expf(s_ms[k][0] - M);
  float wt = __expf(m - M);  // 0 for warps that saw no rows (m = -inf)
#pragma unroll
  for (int j = 0; j < 8; j++) {
    float4 v = make_float4(acc[j].x * wt, acc[j].y * wt, acc[j].z * wt, acc[j].w * wt);
    *reinterpret_cast<float4*>(&s_acc[wp][j * 128 + lane * 4]) = v;
  }
  __syncthreads();

  int c4 = tid * 4;
  float4 sum = make_float4(0.f, 0.f, 0.f, 0.f);
#pragma unroll
  for (int k = 0; k < 8; k++) {
    float4 v = *reinterpret_cast<const float4*>(&s_acc[k][c4]);
    sum.x += v.x; sum.y += v.y; sum.z += v.z; sum.w += v.w;
  }
  float inv = 1.f / S;
  float4 cw = make_float4(sum.x * inv, sum.y * inv, sum.z * inv, sum.w * inv);
  *reinterpret_cast<float4*>(g_cw + (b * T + t) * D + c4) = cw;

  // turn score: q_t . cw (block reduce)
  float4 qt = *reinterpret_cast<const float4*>(g_q + (B + b) * D + c4);
  float tp = fmaf(qt.x, cw.x, fmaf(qt.y, cw.y, fmaf(qt.z, cw.z, qt.w * cw.w)));
#pragma unroll
  for (int off = 16; off; off >>= 1) tp += __shfl_down_sync(0xffffffffu, tp, off);
  if (lane == 0) s_ms[wp][0] = tp;
  __syncthreads();
  if (tid == 0) {
    float v = 0.f;
#pragma unroll
    for (int k = 0; k < 8; k++) v += s_ms[k][0];
    g_ts[b * T + t] = v;
  }

  // ---- ticket: last CTA of batch b performs the turn combine ----
  __shared__ int s_last;
  __threadfence();  // release our g_cw/g_ts writes
  __syncthreads();  // all threads' stores issued before the ticket
  if (tid == 0) s_last = (atomicAdd(&g_cnt[b], 1) == nt - 1);
  __syncthreads();
  if (!s_last) return;
  __threadfence();  // acquire: observe all other CTAs' writes for batch b

  __shared__ float attw[T];
  if (tid < 32) {  // T == 32; masked turns get weight exactly 0
    float s = (tid < nt) ? g_ts[b * T + tid] : -CUDART_INF_F;
    float mx = s;
#pragma unroll
    for (int off = 16; off; off >>= 1)
      mx = fmaxf(mx, __shfl_xor_sync(0xffffffffu, mx, off));
    float e = (tid < nt) ? __expf(s - mx) : 0.f;
    float sm = e;
#pragma unroll
    for (int off = 16; off; off >>= 1)
      sm += __shfl_xor_sync(0xffffffffu, sm, off);
    attw[tid] = e / sm;
  }
  __syncthreads();

  // weighted combine over 32 turns (masked rows of g_cw are exactly 0)
  float4 o0 = make_float4(0.f, 0.f, 0.f, 0.f), o1 = o0, o2 = o0, o3 = o0;
  const float* cwb = g_cw + (long)b * T * D + c4;
#pragma unroll
  for (int tt = 0; tt < T; tt += 4) {
    float a0 = attw[tt], a1 = attw[tt + 1], a2 = attw[tt + 2], a3 = attw[tt + 3];
    float4 v0 = *reinterpret_cast<const float4*>(cwb + (long)tt * D);
    float4 v1 = *reinterpret_cast<const float4*>(cwb + (long)(tt + 1) * D);
    float4 v2 = *reinterpret_cast<const float4*>(cwb + (long)(tt + 2) * D);
    float4 v3 = *reinterpret_cast<const float4*>(cwb + (long)(tt + 3) * D);
    o0.x = fmaf(a0, v0.x, o0.x); o0.y = fmaf(a0, v0.y, o0.y);
    o0.z = fmaf(a0, v0.z, o0.z); o0.w = fmaf(a0, v0.w, o0.w);
    o1.x = fmaf(a1, v1.x, o1.x); o1.y = fmaf(a1, v1.y, o1.y);
    o1.z = fmaf(a1, v1.z, o1.z); o1.w = fmaf(a1, v1.w, o1.w);
    o2.x = fmaf(a2, v2.x, o2.x); o2.y = fmaf(a2, v2.y, o2.y);
    o2.z = fmaf(a2, v2.z, o2.z); o2.w = fmaf(a2, v2.w, o2.w);
    o3.x = fmaf(a3, v3.x, o3.x); o3.y = fmaf(a3, v3.y, o3.y);
    o3.z = fmaf(a3, v3.z, o3.z); o3.w = fmaf(a3, v3.w, o3.w);
  }
  float4 o = make_float4(o0.x + o1.x + o2.x + o3.x, o0.y + o1.y + o2.y + o3.y,
                         o0.z + o1.z + o2.z + o3.z, o0.w + o1.w + o2.w + o3.w);
  *reinterpret_cast<float4*>(out + b * D + c4) = o;
}

// ---------------------------------------------------------------------------
extern "C" void kernel_launch(void* const* d_in, const int* in_sizes, int n_in,
                              void* d_out, int out_size) {
  const float *src = nullptr, *bank = nullptr, *Wword = nullptr, *Wturn = nullptr;
  const int *lens = nullptr, *turns = nullptr;
  for (int i = 0; i < n_in; i++) {
    switch (in_sizes[i]) {
      case B * D:            src  = (const float*)d_in[i]; break;
      case B * T * WW * D:   bank = (const float*)d_in[i]; break;
      case B * T:            lens = (const int*)d_in[i];   break;
      case B:                turns = (const int*)d_in[i];  break;
      case D * D:
        if (!Wword) Wword = (const float*)d_in[i];
        else        Wturn = (const float*)d_in[i];
        break;
      default: break;
    }
  }
  proj_part_kernel<<<dim3(NDBLK, 1, 2), 256>>>(src, Wword, Wturn);
  reduce_q_kernel<<<128, 256>>>();
  attn_kernel<<<dim3(T, B), 256>>>(bank, lens, turns, (float*)d_out);
}